// round 4
// baseline (speedup 1.0000x reference)
#include <cuda_runtime.h>

// Problem constants (fixed shapes for QueryGrouper_57930518888876)
#define BB 8
#define NN 8192
#define MM 2048
#define CC 64
#define KK 32
#define TILE 2048
#define R2 0.01f
#define OUTCH 67            // C + 3

// idx scratch: [B][M][K] int32  (2 MB) — device global, no allocation
__device__ __align__(16) int g_idx[BB * MM * KK];

// ---------------------------------------------------------------------------
// Kernel 1: ball query. One thread per query point; xyz tiled through smem as
// float4{x,y,z,n2}. Records the first K in-radius indices in ascending order
// (exactly what -top_k(-cand) produces), then pads with first hit (or 0).
// Arithmetic replicates reference fp32 rounding:
//   n2/m2 = (x*x + y*y) + z*z            (rn mul/add, left-assoc)
//   dot   = fma(a2,b2, fma(a1,b1, a0*b0)) (ascending-k FMA chain)
//   d2    = fma(-2, dot, m2+n2)           (== (m2+n2) - 2*dot, one rounding)
// ---------------------------------------------------------------------------
__global__ void __launch_bounds__(64)
ball_query_k(const float* __restrict__ new_xyz, const float* __restrict__ xyz)
{
    __shared__ float4 pts[TILE];

    int q = blockIdx.x * 64 + threadIdx.x;     // global query id
    int b = q / MM;
    int m = q % MM;

    const float* nz = new_xyz + (size_t)b * 3 * MM + m;
    float ax = nz[0], ay = nz[MM], az = nz[2 * MM];
    float m2 = __fadd_rn(__fadd_rn(__fmul_rn(ax, ax), __fmul_rn(ay, ay)),
                         __fmul_rn(az, az));

    int* myidx = g_idx + (size_t)q * KK;
    int cnt = 0;

    const float* xb = xyz + (size_t)b * 3 * NN;

    for (int t0 = 0; t0 < NN; t0 += TILE) {
        // cooperative tile load + n2 precompute
        for (int i = threadIdx.x; i < TILE; i += 64) {
            float px = xb[t0 + i];
            float py = xb[NN + t0 + i];
            float pz = xb[2 * NN + t0 + i];
            float n2 = __fadd_rn(__fadd_rn(__fmul_rn(px, px), __fmul_rn(py, py)),
                                 __fmul_rn(pz, pz));
            pts[i] = make_float4(px, py, pz, n2);
        }
        __syncthreads();

        #pragma unroll 8
        for (int i = 0; i < TILE; ++i) {
            float4 p = pts[i];
            float dot = __fmaf_rn(az, p.z, __fmaf_rn(ay, p.y, __fmul_rn(ax, p.x)));
            float t   = __fadd_rn(m2, p.w);
            float d2  = __fmaf_rn(-2.0f, dot, t);
            if (d2 < R2 && cnt < KK) {
                myidx[cnt] = t0 + i;
                cnt++;
            }
        }

        // barrier doubles as early-exit vote (uniform across block)
        if (__syncthreads_and(cnt >= KK)) break;
    }

    int first = (cnt > 0) ? myidx[0] : 0;
    for (int j = cnt; j < KK; ++j) myidx[j] = first;
}

// ---------------------------------------------------------------------------
// Kernel 2: feature gather. One block per (channel, batch). Feature row
// (32 KB) lives in smem; int4 idx loads, float4 coalesced stores.
//   out[b, c, m, j] = feature[b, c, idx[b,m,j]]
// ---------------------------------------------------------------------------
__global__ void __launch_bounds__(256)
gather_feat_k(const float* __restrict__ feat, float* __restrict__ out)
{
    __shared__ float row[NN];

    int c = blockIdx.x;
    int b = blockIdx.y;

    const float4* src = (const float4*)(feat + ((size_t)(b * CC + c)) * NN);
    for (int i = threadIdx.x; i < NN / 4; i += 256)
        ((float4*)row)[i] = src[i];
    __syncthreads();

    const int4* idx4 = (const int4*)g_idx + (size_t)b * (MM * KK / 4);
    float4* dst = (float4*)(out + ((size_t)(b * OUTCH + c)) * (MM * KK));

    for (int g = threadIdx.x; g < MM * KK / 4; g += 256) {
        int4 id = idx4[g];
        dst[g] = make_float4(row[id.x], row[id.y], row[id.z], row[id.w]);
    }
}

// ---------------------------------------------------------------------------
// Kernel 3: xyz gather + recenter. One block per (xyz-channel, batch).
// Writes BOTH group_feature channels 64..66 and the group_xyz output.
//   v = xyz[b, c, idx] - new_xyz[b, c, m]    (rn subtract)
// ---------------------------------------------------------------------------
__global__ void __launch_bounds__(256)
gather_xyz_k(const float* __restrict__ xyz, const float* __restrict__ new_xyz,
             float* __restrict__ out)
{
    __shared__ float row[NN];
    __shared__ float nrow[MM];

    int c = blockIdx.x;
    int b = blockIdx.y;

    const float4* src = (const float4*)(xyz + ((size_t)(b * 3 + c)) * NN);
    for (int i = threadIdx.x; i < NN / 4; i += 256)
        ((float4*)row)[i] = src[i];
    const float4* nsrc = (const float4*)(new_xyz + ((size_t)(b * 3 + c)) * MM);
    for (int i = threadIdx.x; i < MM / 4; i += 256)
        ((float4*)nrow)[i] = nsrc[i];
    __syncthreads();

    const int4* idx4 = (const int4*)g_idx + (size_t)b * (MM * KK / 4);
    const size_t GF_TOTAL = (size_t)BB * OUTCH * MM * KK;   // 35,127,296
    float4* dst1 = (float4*)(out + ((size_t)(b * OUTCH + CC + c)) * (MM * KK));
    float4* dst2 = (float4*)(out + GF_TOTAL + ((size_t)(b * 3 + c)) * (MM * KK));

    for (int g = threadIdx.x; g < MM * KK / 4; g += 256) {
        int4 id = idx4[g];
        float nv = nrow[g >> 3];        // K/4 = 8 float4-groups per query m
        float4 v = make_float4(__fsub_rn(row[id.x], nv),
                               __fsub_rn(row[id.y], nv),
                               __fsub_rn(row[id.z], nv),
                               __fsub_rn(row[id.w], nv));
        dst1[g] = v;
        dst2[g] = v;
    }
}

// ---------------------------------------------------------------------------
// metadata order: new_xyz (8,3,2048), xyz (8,3,8192), feature (8,64,8192),
// use_xyz (always 1 -> group_feature = concat(feat_gather, group_xyz)).
// Output: [group_feature (8,67,2048,32) ; group_xyz (8,3,2048,32)] fp32.
// ---------------------------------------------------------------------------
extern "C" void kernel_launch(void* const* d_in, const int* in_sizes, int n_in,
                              void* d_out, int out_size)
{
    const float* new_xyz = (const float*)d_in[0];
    const float* xyz     = (const float*)d_in[1];
    const float* feat    = (const float*)d_in[2];
    float* out           = (float*)d_out;

    ball_query_k<<<(BB * MM) / 64, 64>>>(new_xyz, xyz);
    gather_feat_k<<<dim3(CC, BB), 256>>>(feat, out);
    gather_xyz_k<<<dim3(3, BB), 256>>>(xyz, new_xyz, out);
}

// round 9
// speedup vs baseline: 2.0642x; 2.0642x over previous
#include <cuda_runtime.h>

// Problem constants (fixed shapes for QueryGrouper_57930518888876)
#define BB 8
#define NN 8192
#define MM 2048
#define CC 64
#define KK 32
#define R2 0.01f
#define OUTCH 67            // C + 3

// Ball-query decomposition
#define QPB 128             // queries per block
#define SEG 8               // segments per query (threads per query)
#define SEGPTS (NN / SEG)   // 1024 points per segment
#define SEGPAIRS (SEGPTS/2) // 512 packed pairs per segment
#define BQ_THREADS (QPB * SEG)  // 1024

// idx scratch: [B][M][K] int32  (2 MB) — device global, no allocation
__device__ __align__(16) int g_idx[BB * MM * KK];

// ---------------- f32x2 packed helpers (elementwise rn, identical rounding) --
__device__ __forceinline__ unsigned long long pack2(float a, float b) {
    unsigned long long r;
    asm("mov.b64 %0, {%1, %2};" : "=l"(r) : "f"(a), "f"(b));
    return r;
}
__device__ __forceinline__ unsigned long long mul2(unsigned long long a, unsigned long long b) {
    unsigned long long r;
    asm("mul.rn.f32x2 %0, %1, %2;" : "=l"(r) : "l"(a), "l"(b));
    return r;
}
__device__ __forceinline__ unsigned long long fma2(unsigned long long a, unsigned long long b, unsigned long long c) {
    unsigned long long r;
    asm("fma.rn.f32x2 %0, %1, %2, %3;" : "=l"(r) : "l"(a), "l"(b), "l"(c));
    return r;
}
__device__ __forceinline__ unsigned long long add2(unsigned long long a, unsigned long long b) {
    unsigned long long r;
    asm("add.rn.f32x2 %0, %1, %2;" : "=l"(r) : "l"(a), "l"(b));
    return r;
}

// ---------------------------------------------------------------------------
// Kernel 1: ball query, segment-split + packed f32x2.
// Block = 1024 threads = 128 queries x 8 segments. Whole batch point tile in
// smem (packed pairs). Thread (q,s) scans points [1024s, 1024s+1024), records
// hit indices (ascending) into a u16 smem buffer. Segments are contiguous
// ascending -> merge is concatenation via counts prefix. Pad with first/0.
//
// Arithmetic replicates reference fp32 rounding exactly:
//   n2/m2 = (x*x + y*y) + z*z
//   dot   = fma(az,pz, fma(ay,py, ax*px))
//   d2    = fma(-2, dot, m2+n2)
// Hit test: sign bit of rn(d2 - R2)  — IEEE sign of subtraction is exact.
// ---------------------------------------------------------------------------
__global__ void __launch_bounds__(BQ_THREADS, 1)
ball_query_k(const float* __restrict__ new_xyz, const float* __restrict__ xyz)
{
    extern __shared__ char smem_raw[];
    ulonglong2* tileXY = (ulonglong2*)smem_raw;                       // 64 KB: {x01, y01}
    ulonglong2* tileZN = (ulonglong2*)(smem_raw + 65536);             // 64 KB: {z01, n01}
    unsigned short* buf = (unsigned short*)(smem_raw + 131072);       // 64 KB: 1024*32 u16
    int* counts = (int*)(smem_raw + 131072 + 65536);                  // 4 KB

    int tid = threadIdx.x;
    int q = tid & (QPB - 1);
    int s = tid >> 7;                      // segment id (warp-uniform)

    int b  = blockIdx.x >> 4;              // 16 q-chunks per batch
    int m  = ((blockIdx.x & 15) * QPB) + q;

    // cooperative tile load + n2 precompute (packed pairs)
    {
        const float* xb = xyz + (size_t)b * 3 * NN;
        const float2* x2 = (const float2*)xb;
        const float2* y2 = (const float2*)(xb + NN);
        const float2* z2 = (const float2*)(xb + 2 * NN);
        for (int j = tid; j < NN / 2; j += BQ_THREADS) {
            float2 px = x2[j], py = y2[j], pz = z2[j];
            float n0 = __fadd_rn(__fadd_rn(__fmul_rn(px.x, px.x), __fmul_rn(py.x, py.x)),
                                 __fmul_rn(pz.x, pz.x));
            float n1 = __fadd_rn(__fadd_rn(__fmul_rn(px.y, px.y), __fmul_rn(py.y, py.y)),
                                 __fmul_rn(pz.y, pz.y));
            ulonglong2 A, Bv;
            A.x  = pack2(px.x, px.y);  A.y  = pack2(py.x, py.y);
            Bv.x = pack2(pz.x, pz.y);  Bv.y = pack2(n0, n1);
            tileXY[j] = A;
            tileZN[j] = Bv;
        }
    }

    // per-query constants
    const float* nz = new_xyz + (size_t)b * 3 * MM + m;
    float ax = nz[0], ay = nz[MM], az = nz[2 * MM];
    float m2 = __fadd_rn(__fadd_rn(__fmul_rn(ax, ax), __fmul_rn(ay, ay)),
                         __fmul_rn(az, az));
    unsigned long long axx = pack2(ax, ax);
    unsigned long long ayy = pack2(ay, ay);
    unsigned long long azz = pack2(az, az);
    unsigned long long m22 = pack2(m2, m2);
    unsigned long long neg2   = pack2(-2.0f, -2.0f);
    unsigned long long negR2p = pack2(-R2, -R2);

    __syncthreads();

    // scan my segment
    unsigned short* mybuf = buf + tid * KK;
    int cnt = 0;
    int jbase = s * SEGPAIRS;
    #pragma unroll 4
    for (int jj = 0; jj < SEGPAIRS; ++jj) {
        int j = jbase + jj;
        ulonglong2 A  = tileXY[j];   // broadcast (warp-uniform address)
        ulonglong2 Bv = tileZN[j];
        unsigned long long dot2 = fma2(azz, Bv.x, fma2(ayy, A.y, mul2(axx, A.x)));
        unsigned long long t2   = add2(m22, Bv.y);
        unsigned long long d22  = fma2(neg2, dot2, t2);
        unsigned long long s2   = add2(d22, negR2p);   // sign bit exact for d2<R2
        int lo = (int)(unsigned int)s2;
        int hi = (int)(s2 >> 32);
        if ((lo | hi) < 0) {
            if (lo < 0 && cnt < KK) mybuf[cnt++] = (unsigned short)(2 * j);
            if (hi < 0 && cnt < KK) mybuf[cnt++] = (unsigned short)(2 * j + 1);
        }
    }
    counts[tid] = cnt;
    __syncthreads();

    // merge: concatenate segments in order (ascending indices preserved)
    int off = 0, total = 0;
    #pragma unroll
    for (int sp = 0; sp < SEG; ++sp) {
        int c = counts[sp * QPB + q];
        total += c;
        if (sp < s) off += c;
    }
    int* dst = g_idx + ((size_t)(b * MM + m)) * KK;
    for (int k = 0; k < cnt && off + k < KK; ++k)
        dst[off + k] = (int)mybuf[k];

    __syncthreads();   // make dst[0] visible for padding

    if (s == 0 && total < KK) {
        int first = (total > 0) ? dst[0] : 0;
        for (int k = total; k < KK; ++k) dst[k] = first;
    }
}

// ---------------------------------------------------------------------------
// Kernel 2: feature gather. One block per (channel, batch). Feature row
// (32 KB) lives in smem; int4 idx loads, float4 coalesced stores.
// ---------------------------------------------------------------------------
__global__ void __launch_bounds__(256)
gather_feat_k(const float* __restrict__ feat, float* __restrict__ out)
{
    __shared__ float row[NN];

    int c = blockIdx.x;
    int b = blockIdx.y;

    const float4* src = (const float4*)(feat + ((size_t)(b * CC + c)) * NN);
    for (int i = threadIdx.x; i < NN / 4; i += 256)
        ((float4*)row)[i] = src[i];
    __syncthreads();

    const int4* idx4 = (const int4*)g_idx + (size_t)b * (MM * KK / 4);
    float4* dst = (float4*)(out + ((size_t)(b * OUTCH + c)) * (MM * KK));

    for (int g = threadIdx.x; g < MM * KK / 4; g += 256) {
        int4 id = idx4[g];
        dst[g] = make_float4(row[id.x], row[id.y], row[id.z], row[id.w]);
    }
}

// ---------------------------------------------------------------------------
// Kernel 3: xyz gather + recenter. Grid (3, B, MSPLIT) for parallelism.
// Writes BOTH group_feature channels 64..66 and the group_xyz output.
// ---------------------------------------------------------------------------
#define MSPLIT 8
#define MCHUNK (MM / MSPLIT)   // 256 queries per block

__global__ void __launch_bounds__(256)
gather_xyz_k(const float* __restrict__ xyz, const float* __restrict__ new_xyz,
             float* __restrict__ out)
{
    __shared__ float row[NN];
    __shared__ float nrow[MCHUNK];

    int c  = blockIdx.x;
    int b  = blockIdx.y;
    int mc = blockIdx.z;          // m-chunk
    int m0 = mc * MCHUNK;

    const float4* src = (const float4*)(xyz + ((size_t)(b * 3 + c)) * NN);
    for (int i = threadIdx.x; i < NN / 4; i += 256)
        ((float4*)row)[i] = src[i];
    const float4* nsrc = (const float4*)(new_xyz + ((size_t)(b * 3 + c)) * MM + m0);
    for (int i = threadIdx.x; i < MCHUNK / 4; i += 256)
        ((float4*)nrow)[i] = nsrc[i];
    __syncthreads();

    const int4* idx4 = (const int4*)g_idx + ((size_t)b * MM + m0) * (KK / 4);
    const size_t GF_TOTAL = (size_t)BB * OUTCH * MM * KK;
    float4* dst1 = (float4*)(out + ((size_t)(b * OUTCH + CC + c)) * (MM * KK) + (size_t)m0 * KK);
    float4* dst2 = (float4*)(out + GF_TOTAL + ((size_t)(b * 3 + c)) * (MM * KK) + (size_t)m0 * KK);

    for (int g = threadIdx.x; g < MCHUNK * KK / 4; g += 256) {
        int4 id = idx4[g];
        float nv = nrow[g >> 3];        // K/4 = 8 float4-groups per query m
        float4 v = make_float4(__fsub_rn(row[id.x], nv),
                               __fsub_rn(row[id.y], nv),
                               __fsub_rn(row[id.z], nv),
                               __fsub_rn(row[id.w], nv));
        dst1[g] = v;
        dst2[g] = v;
    }
}

// ---------------------------------------------------------------------------
// metadata order: new_xyz (8,3,2048), xyz (8,3,8192), feature (8,64,8192),
// use_xyz (always 1). Output: [group_feature (8,67,2048,32) ; group_xyz
// (8,3,2048,32)] fp32.
// ---------------------------------------------------------------------------
extern "C" void kernel_launch(void* const* d_in, const int* in_sizes, int n_in,
                              void* d_out, int out_size)
{
    const float* new_xyz = (const float*)d_in[0];
    const float* xyz     = (const float*)d_in[1];
    const float* feat    = (const float*)d_in[2];
    float* out           = (float*)d_out;

    const int bq_smem = 65536 + 65536 + 65536 + BQ_THREADS * (int)sizeof(int);
    cudaFuncSetAttribute(ball_query_k, cudaFuncAttributeMaxDynamicSharedMemorySize, bq_smem);

    ball_query_k<<<(BB * MM) / QPB, BQ_THREADS, bq_smem>>>(new_xyz, xyz);
    gather_feat_k<<<dim3(CC, BB), 256>>>(feat, out);
    gather_xyz_k<<<dim3(3, BB, MSPLIT), 256>>>(xyz, new_xyz, out);
}